// round 1
// baseline (speedup 1.0000x reference)
#include <cuda_runtime.h>
#include <cuda_bf16.h>
#include <math.h>

#define BATCH 512
#define NTOK  16
#define CDIM  256
#define KCODE 8192
#define NSTAGE 16
#define BNC (BATCH*NTOK*CDIM)   // 2097152

// ---------------- device globals (scratch; no allocations allowed) ----------------
__device__ float  g_fres[BNC];          // residual, [b][n][c] layout (8 MB)
__device__ float  g_fhat[BNC];          // accumulated reconstruction (8 MB)
__device__ float  g_rest[BATCH*NTOK*CDIM]; // pooled rows for current stage (8 MB)
__device__ float  g_t1[BATCH*NTOK];     // per-row ||rest||^2
__device__ float  g_esq[KCODE];         // ||emb_k||^2
__device__ int    g_idx[BATCH*NTOK];    // chosen code per row
__device__ float  g_pd[BATCH*NTOK*64];  // per-(row,kblock) partial min distance
__device__ int    g_pi[BATCH*NTOK*64];  // per-(row,kblock) partial argmin index
__device__ double g_m[NSTAGE];          // per-stage sum of (f_hat - f)^2

// ---------------- init ----------------
__global__ void init_kernel(const float* __restrict__ f) {
    size_t i = (size_t)blockIdx.x * 256 + threadIdx.x;
    g_fres[i] = f[i];
    g_fhat[i] = 0.0f;
    if (i < NSTAGE) g_m[i] = 0.0;
}

// ---------------- e_sq[k] = sum_c emb[k,c]^2 (one warp per k) ----------------
__global__ void esq_kernel(const float* __restrict__ emb) {
    int gw = (blockIdx.x * blockDim.x + threadIdx.x) >> 5;
    int lane = threadIdx.x & 31;
    if (gw >= KCODE) return;
    float s = 0.0f;
    const float* row = emb + (size_t)gw * CDIM;
    #pragma unroll
    for (int c = lane; c < CDIM; c += 32) {
        float v = row[c];
        s = __fmaf_rn(v, v, s);
    }
    #pragma unroll
    for (int o = 16; o; o >>= 1) s += __shfl_down_sync(0xffffffffu, s, o);
    if (lane == 0) g_esq[gw] = s;
}

// ---------------- pool: rest[b,p,c] = sum_{n in bin} w * fres[b,n,c]; also t1 ----------------
__global__ void pool_kernel(int pn) {
    int row = blockIdx.x;                 // row = b*pn + p
    int b = row / pn, p = row - b * pn;
    int s = (p * NTOK) / pn;
    int e = ((p + 1) * NTOK + pn - 1) / pn;       // ceil
    float w = (float)(1.0 / (double)(e - s));     // matches np.float32(1.0/(e-s))
    int c = threadIdx.x;
    float acc = 0.0f;
    for (int n = s; n < e; n++)
        acc = __fmaf_rn(w, g_fres[((size_t)b * NTOK + n) * CDIM + c], acc);
    g_rest[(size_t)row * CDIM + c] = acc;

    // t1 = sum_c rest^2 (products rounded fp32 like jnp.sum(rest*rest))
    float sq = __fmul_rn(acc, acc);
    __shared__ float sm[8];
    int lane = threadIdx.x & 31, wid = threadIdx.x >> 5;
    #pragma unroll
    for (int o = 16; o; o >>= 1) sq += __shfl_down_sync(0xffffffffu, sq, o);
    if (lane == 0) sm[wid] = sq;
    __syncthreads();
    if (wid == 0) {
        float v = (lane < 8) ? sm[lane] : 0.0f;
        #pragma unroll
        for (int o = 4; o; o >>= 1) v += __shfl_down_sync(0xffffffffu, v, o);
        if (lane == 0) g_t1[row] = v;
    }
}

// ---------------- distance GEMM + per-tile argmin ----------------
// Tile: 128 rows x 128 codes, inner C chunked by 32. 256 threads, 8x8 microtile.
// d = (t1 + e_sq[k]) - 2*dot  with reference rounding structure; first-index ties.
__global__ __launch_bounds__(256, 2) void dist_kernel(const float* __restrict__ emb) {
    __shared__ float As[32][129];   // [c][m]
    __shared__ float Bs[32][129];   // [c][k]
    int r0 = blockIdx.x * 128;
    int k0 = blockIdx.y * 128;
    int t  = threadIdx.x;
    int tx = t & 15, ty = t >> 4;

    float acc[8][8];
    #pragma unroll
    for (int i = 0; i < 8; i++)
        #pragma unroll
        for (int j = 0; j < 8; j++) acc[i][j] = 0.0f;

    for (int cb = 0; cb < CDIM; cb += 32) {
        #pragma unroll
        for (int p = 0; p < 16; p++) {
            int idx = t + 256 * p;
            int c = idx & 31, m = idx >> 5;
            As[c][m] = g_rest[(size_t)(r0 + m) * CDIM + cb + c];
            Bs[c][m] = emb[(size_t)(k0 + m) * CDIM + cb + c];
        }
        __syncthreads();
        #pragma unroll
        for (int c = 0; c < 32; c++) {
            float a[8], bv[8];
            #pragma unroll
            for (int i = 0; i < 8; i++) a[i] = As[c][ty + 16 * i];
            #pragma unroll
            for (int j = 0; j < 8; j++) bv[j] = Bs[c][tx + 16 * j];
            #pragma unroll
            for (int i = 0; i < 8; i++)
                #pragma unroll
                for (int j = 0; j < 8; j++)
                    acc[i][j] = __fmaf_rn(a[i], bv[j], acc[i][j]);
        }
        __syncthreads();
    }

    #pragma unroll
    for (int i = 0; i < 8; i++) {
        int row = r0 + ty + 16 * i;
        float t1 = g_t1[row];
        float bd = INFINITY;
        int   bk = 0x7fffffff;
        #pragma unroll
        for (int j = 0; j < 8; j++) {
            int k = k0 + tx + 16 * j;
            float tt = __fadd_rn(t1, g_esq[k]);
            float d  = __fmaf_rn(-2.0f, acc[i][j], tt);  // == fl(tt - 2*dot), 2*dot exact
            if (d < bd || (d == bd && k < bk)) { bd = d; bk = k; }
        }
        #pragma unroll
        for (int o = 8; o; o >>= 1) {
            float od = __shfl_down_sync(0xffffffffu, bd, o, 16);
            int   ok = __shfl_down_sync(0xffffffffu, bk, o, 16);
            if (od < bd || (od == bd && ok < bk)) { bd = od; bk = ok; }
        }
        if (tx == 0) {
            g_pd[(size_t)row * 64 + blockIdx.y] = bd;
            g_pi[(size_t)row * 64 + blockIdx.y] = bk;
        }
    }
}

// ---------------- reduce argmin across 64 k-blocks ----------------
__global__ void argmin_reduce_kernel() {
    int row = blockIdx.x * 8 + threadIdx.y;
    int l = threadIdx.x;
    size_t base = (size_t)row * 64;
    float bd = g_pd[base + l];      int bk = g_pi[base + l];
    float d2 = g_pd[base + l + 32]; int k2 = g_pi[base + l + 32];
    if (d2 < bd || (d2 == bd && k2 < bk)) { bd = d2; bk = k2; }
    #pragma unroll
    for (int o = 16; o; o >>= 1) {
        float od = __shfl_down_sync(0xffffffffu, bd, o);
        int   ok = __shfl_down_sync(0xffffffffu, bk, o);
        if (od < bd || (od == bd && ok < bk)) { bd = od; bk = ok; }
    }
    if (l == 0) g_idx[row] = bk;
}

// ---------------- gather + linear upsample + update f_hat/f_rest + stage stats ----------------
__global__ void update_kernel(const float* __restrict__ f, const float* __restrict__ emb,
                              int pn, int stage) {
    int bn = blockIdx.x;               // b*16 + n
    int n = bn & 15, b = bn >> 4;
    int c = threadIdx.x;

    // replicate _up_mat exactly (float64 math, float32 storage)
    double scale = (double)pn / 16.0;
    double pos = ((double)n + 0.5) * scale - 0.5;
    if (pos < 0.0) pos = 0.0;
    int i0 = (int)floor(pos);
    if (i0 > pn - 1) i0 = pn - 1;
    int i1 = (i0 + 1 < pn) ? i0 + 1 : pn - 1;
    double frac = pos - (double)i0;

    int base = b * pn;
    float hv;
    if (i1 == i0) {
        float wc = (float)((double)((float)(1.0 - frac)) + frac); // W[j,i0] += (1-frac); += frac
        int k0 = g_idx[base + i0];
        hv = __fmul_rn(wc, emb[(size_t)k0 * CDIM + c]);
    } else {
        float w0 = (float)(1.0 - frac);
        float w1 = (float)frac;
        int k0 = g_idx[base + i0];
        int k1 = g_idx[base + i1];
        hv = __fadd_rn(__fmul_rn(w0, emb[(size_t)k0 * CDIM + c]),
                       __fmul_rn(w1, emb[(size_t)k1 * CDIM + c]));
    }

    size_t off = (size_t)bn * CDIM + c;
    float fh = __fadd_rn(g_fhat[off], hv);
    g_fhat[off] = fh;
    g_fres[off] = __fadd_rn(g_fres[off], -hv);

    float diff = __fadd_rn(fh, -f[off]);
    double v = (double)diff * (double)diff;

    __shared__ double sm[8];
    int lane = threadIdx.x & 31, wid = threadIdx.x >> 5;
    #pragma unroll
    for (int o = 16; o; o >>= 1) v += __shfl_down_sync(0xffffffffu, v, o);
    if (lane == 0) sm[wid] = v;
    __syncthreads();
    if (wid == 0) {
        double w = (lane < 8) ? sm[lane] : 0.0;
        #pragma unroll
        for (int o = 4; o; o >>= 1) w += __shfl_down_sync(0xffffffffu, w, o);
        if (lane == 0) atomicAdd(&g_m[stage], w);
    }
}

// ---------------- outputs ----------------
// STE: out = fl(fl(f_hat - f) + f)  (NOT simplified: the cancellation is inexact)
__global__ void out_main_kernel(const float* __restrict__ f, float* __restrict__ out) {
    size_t i = (size_t)blockIdx.x * 256 + threadIdx.x;
    out[i] = __fadd_rn(__fadd_rn(g_fhat[i], -f[i]), f[i]);
}

__global__ void out_scalar_kernel(float* __restrict__ out) {
    if (threadIdx.x == 0 && blockIdx.x == 0) {
        float c = 0.0f, q = 0.0f;
        for (int s = 0; s < NSTAGE; s++) {
            float m = (float)(g_m[s] * (1.0 / 2097152.0));  // mean over B*C*N = 2^21
            c = __fadd_rn(c, __fmul_rn(0.25f, m));
            q = __fadd_rn(q, m);
        }
        out[BNC]     = __fdiv_rn(c, 16.0f);
        out[BNC + 1] = __fdiv_rn(q, 16.0f);
    }
}

// ---------------- launch ----------------
extern "C" void kernel_launch(void* const* d_in, const int* in_sizes, int n_in,
                              void* d_out, int out_size) {
    const float* f   = (const float*)d_in[0];
    const float* emb = (const float*)d_in[1];
    float* out = (float*)d_out;

    init_kernel<<<BNC / 256, 256>>>(f);
    esq_kernel<<<(KCODE * 32) / 256, 256>>>(emb);

    for (int pn = 1; pn <= NTOK; pn++) {
        int rows = BATCH * pn;
        pool_kernel<<<rows, 256>>>(pn);
        dim3 dg(rows / 128, KCODE / 128);
        dist_kernel<<<dg, 256>>>(emb);
        argmin_reduce_kernel<<<rows / 8, dim3(32, 8)>>>();
        update_kernel<<<BATCH * NTOK, 256>>>(f, emb, pn, pn - 1);
    }

    out_main_kernel<<<BNC / 256, 256>>>(f, out);
    out_scalar_kernel<<<1, 32>>>(out);
}